// round 1
// baseline (speedup 1.0000x reference)
#include <cuda_runtime.h>
#include <math.h>

#define EPS 1e-5f
#define MAX_BK 32768

// ---- scratch (device globals; no allocation allowed) ----
__device__ float4 g_sums[MAX_BK];          // per-bin {sum fx, sum fy, sum xx, sum yy}
__device__ float  g_cnt [MAX_BK];          // per-bin count
__device__ float  g_tmp1[(size_t)MAX_BK * 64];
__device__ float  g_tmp2[(size_t)MAX_BK * 32];
__device__ float  g_st1 [128];             // [0:64) sum, [64:128) sumsq of layer-1 pre-BN
__device__ float  g_st2 [64];              // [0:32) sum, [32:64) sumsq of layer-2 pre-BN

// ---- vectorized global reductions (sm_90+: red.global.add.v4.f32) ----
__device__ __forceinline__ void red_v4(float4* p, float a, float b, float c, float d) {
    asm volatile("red.global.add.v4.f32 [%0], {%1,%2,%3,%4};"
                 :: "l"(p), "f"(a), "f"(b), "f"(c), "f"(d) : "memory");
}
__device__ __forceinline__ void red_f(float* p, float v) {
    asm volatile("red.global.add.f32 [%0], %1;" :: "l"(p), "f"(v) : "memory");
}

// ---- kernel 0: zero accumulators (graph replays must be deterministic) ----
__global__ void zero_k(int bk) {
    int i = blockIdx.x * blockDim.x + threadIdx.x;
    if (i < bk) { g_sums[i] = make_float4(0.f, 0.f, 0.f, 0.f); g_cnt[i] = 0.f; }
    if (i < 128) g_st1[i] = 0.f;
    if (i < 64)  g_st2[i] = 0.f;
}

// ---- kernel 1: pooling scatter. 4 pixels/thread (vector loads), 2 REDs/pixel ----
__global__ void pool_k(const int*   __restrict__ labels,
                       const float* __restrict__ fxp,
                       const float* __restrict__ fyp,
                       int P, int h, int K, float sx, float sy, int N4) {
    int g = blockIdx.x * blockDim.x + threadIdx.x;
    if (g >= N4) return;
    int4   lb = ((const int4*)  labels)[g];
    float4 vx = ((const float4*)fxp)[g];
    float4 vy = ((const float4*)fyp)[g];
    int p0  = g << 2;
    int b   = p0 / P;           // P, h multiples of 4 -> 4-pack stays in one row/batch
    int pin = p0 - b * P;
    int i   = pin / h;
    int j   = pin - i * h;
    float xx = (float)i * sx - 1.f;
    float y0 = (float)j * sy - 1.f;
    int base = b * K;
    red_v4(&g_sums[base + lb.x], vx.x, vy.x, xx, y0);
    red_v4(&g_sums[base + lb.y], vx.y, vy.y, xx, y0 + sy);
    red_v4(&g_sums[base + lb.z], vx.z, vy.z, xx, y0 + 2.f * sy);
    red_v4(&g_sums[base + lb.w], vx.w, vy.w, xx, y0 + 3.f * sy);
    red_f(&g_cnt[base + lb.x], 1.f);
    red_f(&g_cnt[base + lb.y], 1.f);
    red_f(&g_cnt[base + lb.z], 1.f);
    red_f(&g_cnt[base + lb.w], 1.f);
}

// ---- kernel 2: build x[5], conv1d(5->64), accumulate BN1 batch stats ----
__global__ void mlp1_k(const int*   __restrict__ fidx,
                       const int*   __restrict__ nfp,
                       const float* __restrict__ cw,   // [64,5]
                       const float* __restrict__ cb,   // [64]
                       int K, int BK) {
    __shared__ float wsm[320];
    __shared__ float bsm[64];
    __shared__ float ssum[64], ssq[64];
    int t = threadIdx.x;
    for (int q = t; q < 320; q += 256) wsm[q] = cw[q];
    if (t < 64) { bsm[t] = cb[t]; ssum[t] = 0.f; ssq[t] = 0.f; }
    __syncthreads();

    int tkn = blockIdx.x * blockDim.x + t;
    bool act = (tkn < BK);
    float x0 = 0.f, x1 = 0.f, x2 = 0.f, x3 = 0.f, x4 = 0.f;
    if (act) {
        int nf = nfp ? *nfp : 100;
        float invnf = 1.f / (float)(nf - 1);
        int b = tkn / K;
        x0 = (float)fidx[b] * invnf;
        float c  = fmaxf(g_cnt[tkn], 1.f);
        float ic = 1.f / c;
        float4 s = g_sums[tkn];
        x1 = s.x * ic; x2 = s.y * ic; x3 = s.z * ic; x4 = s.w * ic;
    }
    float o[64];
#pragma unroll
    for (int c2 = 0; c2 < 64; c2++) {
        float v = fmaf(wsm[c2*5+4], x4,
                  fmaf(wsm[c2*5+3], x3,
                  fmaf(wsm[c2*5+2], x2,
                  fmaf(wsm[c2*5+1], x1,
                  fmaf(wsm[c2*5+0], x0, bsm[c2])))));
        o[c2] = act ? v : 0.f;
    }
    if (act) {
        float4* dst = (float4*)&g_tmp1[(size_t)tkn * 64];
#pragma unroll
        for (int q = 0; q < 16; q++)
            dst[q] = make_float4(o[4*q], o[4*q+1], o[4*q+2], o[4*q+3]);
    }
    // per-channel batch stats: warp shuffle-reduce, smem combine, global RED
#pragma unroll
    for (int c2 = 0; c2 < 64; c2++) {
        float v = o[c2], v2 = v * v;
#pragma unroll
        for (int off = 16; off; off >>= 1) {
            v  += __shfl_xor_sync(0xffffffffu, v,  off);
            v2 += __shfl_xor_sync(0xffffffffu, v2, off);
        }
        if ((t & 31) == 0) { atomicAdd(&ssum[c2], v); atomicAdd(&ssq[c2], v2); }
    }
    __syncthreads();
    if (t < 64) { red_f(&g_st1[t], ssum[t]); red_f(&g_st1[64 + t], ssq[t]); }
}

// ---- kernel 3: BN1+ReLU, linear(64->32), accumulate BN2 batch stats ----
__global__ void mlp2_k(const float* __restrict__ lw,   // [32,64]
                       const float* __restrict__ lbp,  // [32]
                       const float* __restrict__ g1,
                       const float* __restrict__ b1,
                       int BK, float invN) {
    __shared__ float wsm[2048];
    __shared__ float scale[64], shift[64];
    __shared__ float lbs[32], ssum[32], ssq[32];
    int t = threadIdx.x;
    for (int q = t; q < 2048; q += 256) wsm[q] = lw[q];
    if (t < 64) {
        float m   = g_st1[t] * invN;
        float var = g_st1[64 + t] * invN - m * m;
        float sc  = g1[t] * rsqrtf(var + EPS);
        scale[t] = sc; shift[t] = b1[t] - m * sc;
    }
    if (t < 32) { lbs[t] = lbp[t]; ssum[t] = 0.f; ssq[t] = 0.f; }
    __syncthreads();

    int tkn = blockIdx.x * blockDim.x + t;
    bool act = (tkn < BK);
    float z[64];
    if (act) {
        const float4* src = (const float4*)&g_tmp1[(size_t)tkn * 64];
#pragma unroll
        for (int q = 0; q < 16; q++) {
            float4 v = src[q];
            z[4*q+0] = fmaxf(fmaf(v.x, scale[4*q+0], shift[4*q+0]), 0.f);
            z[4*q+1] = fmaxf(fmaf(v.y, scale[4*q+1], shift[4*q+1]), 0.f);
            z[4*q+2] = fmaxf(fmaf(v.z, scale[4*q+2], shift[4*q+2]), 0.f);
            z[4*q+3] = fmaxf(fmaf(v.w, scale[4*q+3], shift[4*q+3]), 0.f);
        }
    } else {
#pragma unroll
        for (int q = 0; q < 64; q++) z[q] = 0.f;
    }
    float o[32];
#pragma unroll
    for (int o2 = 0; o2 < 32; o2++) {
        float acc = act ? lbs[o2] : 0.f;
#pragma unroll
        for (int c = 0; c < 64; c++) acc = fmaf(z[c], wsm[o2*64 + c], acc);
        o[o2] = acc;
    }
    if (act) {
        float4* dst = (float4*)&g_tmp2[(size_t)tkn * 32];
#pragma unroll
        for (int q = 0; q < 8; q++)
            dst[q] = make_float4(o[4*q], o[4*q+1], o[4*q+2], o[4*q+3]);
    }
#pragma unroll
    for (int o2 = 0; o2 < 32; o2++) {
        float v = o[o2], v2 = v * v;
#pragma unroll
        for (int off = 16; off; off >>= 1) {
            v  += __shfl_xor_sync(0xffffffffu, v,  off);
            v2 += __shfl_xor_sync(0xffffffffu, v2, off);
        }
        if ((t & 31) == 0) { atomicAdd(&ssum[o2], v); atomicAdd(&ssq[o2], v2); }
    }
    __syncthreads();
    if (t < 32) { red_f(&g_st2[t], ssum[t]); red_f(&g_st2[32 + t], ssq[t]); }
}

// ---- kernel 4: BN2+ReLU, L2 normalize, write output ----
__global__ void mlp3_k(const float* __restrict__ g2,
                       const float* __restrict__ b2,
                       float* __restrict__ out,
                       int BK, float invN) {
    __shared__ float scale[32], shift[32];
    int t = threadIdx.x;
    if (t < 32) {
        float m   = g_st2[t] * invN;
        float var = g_st2[32 + t] * invN - m * m;
        float sc  = g2[t] * rsqrtf(var + EPS);
        scale[t] = sc; shift[t] = b2[t] - m * sc;
    }
    __syncthreads();
    int tkn = blockIdx.x * blockDim.x + t;
    if (tkn >= BK) return;
    const float4* src = (const float4*)&g_tmp2[(size_t)tkn * 32];
    float v[32];
    float nrm = 0.f;
#pragma unroll
    for (int q = 0; q < 8; q++) {
        float4 a = src[q];
        float e0 = fmaxf(fmaf(a.x, scale[4*q+0], shift[4*q+0]), 0.f);
        float e1 = fmaxf(fmaf(a.y, scale[4*q+1], shift[4*q+1]), 0.f);
        float e2 = fmaxf(fmaf(a.z, scale[4*q+2], shift[4*q+2]), 0.f);
        float e3 = fmaxf(fmaf(a.w, scale[4*q+3], shift[4*q+3]), 0.f);
        nrm += e0*e0 + e1*e1 + e2*e2 + e3*e3;
        v[4*q+0]=e0; v[4*q+1]=e1; v[4*q+2]=e2; v[4*q+3]=e3;
    }
    float inv = 1.f / fmaxf(sqrtf(nrm), 1e-8f);
    float4* dst = (float4*)&out[(size_t)tkn * 32];
#pragma unroll
    for (int q = 0; q < 8; q++)
        dst[q] = make_float4(v[4*q]*inv, v[4*q+1]*inv, v[4*q+2]*inv, v[4*q+3]*inv);
}

extern "C" void kernel_launch(void* const* d_in, const int* in_sizes, int n_in,
                              void* d_out, int out_size) {
    const int*   labels = (const int*)  d_in[0];
    const float* fx     = (const float*)d_in[1];
    const float* fy     = (const float*)d_in[2];
    const int*   fidx   = (const int*)  d_in[3];
    int wi = 4;
    const int* nfp = nullptr;
    if (n_in >= 14) {           // n_frames / n_labels passed as device scalars
        nfp = (const int*)d_in[4];
        wi = 6;
    }
    const float* cw = (const float*)d_in[wi + 0];
    const float* cb = (const float*)d_in[wi + 1];
    const float* g1 = (const float*)d_in[wi + 2];
    const float* b1 = (const float*)d_in[wi + 3];
    const float* lw = (const float*)d_in[wi + 4];
    const float* lb = (const float*)d_in[wi + 5];
    const float* g2 = (const float*)d_in[wi + 6];
    const float* b2 = (const float*)d_in[wi + 7];

    int B  = in_sizes[3];                 // frame_idx element count
    int Np = in_sizes[0];                 // B * w * h
    int P  = Np / B;
    int BK = out_size / 32;               // B * n_labels
    int K  = BK / B;
    int hh = (int)(sqrt((double)P) + 0.5);  // square images (512x512)
    int ww = P / hh;
    float sx = 2.f / (float)(ww - 1);
    float sy = 2.f / (float)(hh - 1);
    int N4 = Np / 4;

    zero_k<<<(BK + 255) / 256, 256>>>(BK);
    pool_k<<<(N4 + 255) / 256, 256>>>(labels, fx, fy, P, hh, K, sx, sy, N4);
    int gb = (BK + 255) / 256;
    float invN = 1.f / (float)BK;
    mlp1_k<<<gb, 256>>>(fidx, nfp, cw, cb, K, BK);
    mlp2_k<<<gb, 256>>>(lw, lb, g1, b1, BK, invN);
    mlp3_k<<<gb, 256>>>(g2, b2, (float*)d_out, BK, invN);
}

// round 3
// speedup vs baseline: 2.6752x; 2.6752x over previous
#include <cuda_runtime.h>
#include <math.h>

#define EPS 1e-5f
#define MAX_BK 32768

typedef unsigned long long u64;

// ---- scratch (device globals; no allocation allowed) ----
__device__ float4 g_sums[MAX_BK];          // per-bin {sum fx, sum fy, sum_i, sum_j}
__device__ float  g_cnt [MAX_BK];          // per-bin count
__device__ float  g_tmp1[(size_t)MAX_BK * 64];
__device__ float  g_tmp2[(size_t)MAX_BK * 32];
__device__ float  g_st1 [128];             // [0:64) sum, [64:128) sumsq of layer-1 pre-BN
__device__ float  g_st2 [64];              // [0:32) sum, [32:64) sumsq of layer-2 pre-BN

// ---- global reductions ----
__device__ __forceinline__ void red_v4(float4* p, float a, float b, float c, float d) {
    asm volatile("red.global.add.v4.f32 [%0], {%1,%2,%3,%4};"
                 :: "l"(p), "f"(a), "f"(b), "f"(c), "f"(d) : "memory");
}
__device__ __forceinline__ void red_f(float* p, float v) {
    asm volatile("red.global.add.f32 [%0], %1;" :: "l"(p), "f"(v) : "memory");
}

// ---- kernel 0: zero accumulators ----
__global__ void zero_k(int bk) {
    int i = blockIdx.x * blockDim.x + threadIdx.x;
    if (i < bk) { g_sums[i] = make_float4(0.f, 0.f, 0.f, 0.f); g_cnt[i] = 0.f; }
    if (i < 128) g_st1[i] = 0.f;
    if (i < 64)  g_st2[i] = 0.f;
}

// ---- pool A: smem-privatized. CTA = 4096 contiguous pixels of one batch image ----
// smem atomics: fx (f32), fy (f32), packed u64 (sum_i<<40 | sum_j<<16 | count).
__global__ void pool_priv_k(const int*   __restrict__ labels,
                            const float* __restrict__ fxp,
                            const float* __restrict__ fyp,
                            int P, int h, int K, int cpb) {
    extern __shared__ char sm[];
    u64*   s_ij = (u64*)sm;                 // [K]
    float* s_fx = (float*)(sm + K * 8);     // [K]
    float* s_fy = s_fx + K;                 // [K]
    int t = threadIdx.x;
    for (int q = t; q < K; q += 256) { s_ij[q] = 0ull; s_fx[q] = 0.f; s_fy[q] = 0.f; }
    __syncthreads();

    int b     = blockIdx.x / cpb;
    int chunk = blockIdx.x - b * cpb;       // which 4096-pixel chunk
    int base4 = (b * P + chunk * 4096) >> 2;  // float4 index base
    // 4096 pixels = 1024 float4 groups = 4 iters of 256 threads
#pragma unroll
    for (int it = 0; it < 4; it++) {
        int g4 = base4 + it * 256 + t;
        int4   lb = ((const int4*)  labels)[g4];
        float4 vx = ((const float4*)fxp)[g4];
        float4 vy = ((const float4*)fyp)[g4];
        int p0  = g4 << 2;
        int pin = p0 - b * P;
        int i   = pin / h;
        int j   = pin - i * h;              // h % 4 == 0 -> 4-pack same row
        u64 bi = ((u64)i << 40) | 1ull;
        atomicAdd(&s_fx[lb.x], vx.x); atomicAdd(&s_fy[lb.x], vy.x);
        atomicAdd(&s_ij[lb.x], bi | ((u64)(j + 0) << 16));
        atomicAdd(&s_fx[lb.y], vx.y); atomicAdd(&s_fy[lb.y], vy.y);
        atomicAdd(&s_ij[lb.y], bi | ((u64)(j + 1) << 16));
        atomicAdd(&s_fx[lb.z], vx.z); atomicAdd(&s_fy[lb.z], vy.z);
        atomicAdd(&s_ij[lb.z], bi | ((u64)(j + 2) << 16));
        atomicAdd(&s_fx[lb.w], vx.w); atomicAdd(&s_fy[lb.w], vy.w);
        atomicAdd(&s_ij[lb.w], bi | ((u64)(j + 3) << 16));
    }
    __syncthreads();
    // flush to global bins
    for (int q = t; q < K; q += 256) {
        u64 p = s_ij[q];
        if (p) {
            float si = (float)(unsigned)(p >> 40);
            float sj = (float)(unsigned)((p >> 16) & 0xFFFFFFull);
            float c  = (float)(unsigned)(p & 0xFFFFull);
            red_v4(&g_sums[b * K + q], s_fx[q], s_fy[q], si, sj);
            red_f(&g_cnt[b * K + q], c);
        }
    }
}

// ---- pool B fallback: direct global REDs (any shape) ----
__global__ void pool_gl_k(const int*   __restrict__ labels,
                          const float* __restrict__ fxp,
                          const float* __restrict__ fyp,
                          int P, int h, int K, int Np) {
    int p0 = blockIdx.x * blockDim.x + threadIdx.x;
    if (p0 >= Np) return;
    int b   = p0 / P;
    int pin = p0 - b * P;
    int i   = pin / h;
    int j   = pin - i * h;
    int l   = labels[p0];
    red_v4(&g_sums[b * K + l], fxp[p0], fyp[p0], (float)i, (float)j);
    red_f(&g_cnt[b * K + l], 1.f);
}

// ---- mlp1: warp-per-token (8 tokens/warp), lane covers channels {lane, lane+32} ----
__global__ void mlp1_k(const int*   __restrict__ fidx,
                       const int*   __restrict__ nfp,
                       const float* __restrict__ cw,   // [64,5]
                       const float* __restrict__ cb,   // [64]
                       int K, int BK, float sx, float sy) {
    __shared__ float wsm[320];
    __shared__ float bsm[64];
    __shared__ float ssum[64], ssq[64];
    int t = threadIdx.x, lane = t & 31, w = t >> 5;
    for (int q = t; q < 320; q += 256) wsm[q] = cw[q];
    if (t < 64) { bsm[t] = cb[t]; ssum[t] = 0.f; ssq[t] = 0.f; }
    __syncthreads();

    int nf = nfp ? *nfp : 100;
    float invnf = 1.f / (float)(nf - 1);
    int tok0 = blockIdx.x * 64 + w * 8;
    float sa = 0.f, sa2 = 0.f, sb = 0.f, sb2 = 0.f;
    int ca = lane, cb2 = lane + 32;
#pragma unroll
    for (int tt = 0; tt < 8; tt++) {
        int tkn = tok0 + tt;
        if (tkn >= BK) break;
        int bb = tkn / K;
        float x0 = (float)__ldg(&fidx[bb]) * invnf;
        float c  = fmaxf(g_cnt[tkn], 1.f);
        float ic = 1.f / c;
        float4 s = g_sums[tkn];
        float x1 = s.x * ic, x2 = s.y * ic;
        float x3 = fmaf(s.z * ic, sx, -1.f);   // mean xx
        float x4 = fmaf(s.w * ic, sy, -1.f);   // mean yy
        float oa = fmaf(wsm[ca*5+4], x4, fmaf(wsm[ca*5+3], x3, fmaf(wsm[ca*5+2], x2,
                   fmaf(wsm[ca*5+1], x1, fmaf(wsm[ca*5+0], x0, bsm[ca])))));
        float ob = fmaf(wsm[cb2*5+4], x4, fmaf(wsm[cb2*5+3], x3, fmaf(wsm[cb2*5+2], x2,
                   fmaf(wsm[cb2*5+1], x1, fmaf(wsm[cb2*5+0], x0, bsm[cb2])))));
        g_tmp1[(size_t)tkn * 64 + ca]  = oa;
        g_tmp1[(size_t)tkn * 64 + cb2] = ob;
        sa += oa; sa2 = fmaf(oa, oa, sa2);
        sb += ob; sb2 = fmaf(ob, ob, sb2);
    }
    atomicAdd(&ssum[ca], sa);  atomicAdd(&ssq[ca], sa2);
    atomicAdd(&ssum[cb2], sb); atomicAdd(&ssq[cb2], sb2);
    __syncthreads();
    if (t < 64) { red_f(&g_st1[t], ssum[t]); red_f(&g_st1[64 + t], ssq[t]); }
}

// ---- mlp2: warp-per-token, lane = out channel; shuffle-broadcast inner product ----
__global__ void mlp2_k(const float* __restrict__ lw,   // [32,64]
                       const float* __restrict__ lbp,  // [32]
                       const float* __restrict__ g1,
                       const float* __restrict__ b1,
                       int BK, float invN) {
    __shared__ float wT[2048];               // transposed: wT[c*32 + o]
    __shared__ float scale[64], shift[64];
    __shared__ float lbs[32], ssum[32], ssq[32];
    int t = threadIdx.x, lane = t & 31, w = t >> 5;
    for (int q = t; q < 2048; q += 256) {
        int o = q / 64, c = q - o * 64;
        wT[c * 32 + o] = lw[q];
    }
    if (t < 64) {
        float m   = g_st1[t] * invN;
        float var = g_st1[64 + t] * invN - m * m;
        float sc  = g1[t] * rsqrtf(var + EPS);
        scale[t] = sc; shift[t] = b1[t] - m * sc;
    }
    if (t < 32) { lbs[t] = lbp[t]; ssum[t] = 0.f; ssq[t] = 0.f; }
    __syncthreads();

    float sc_lo = scale[lane], sh_lo = shift[lane];
    float sc_hi = scale[lane + 32], sh_hi = shift[lane + 32];
    float bias = lbs[lane];
    int tok0 = blockIdx.x * 64 + w * 8;
    float s1 = 0.f, s2 = 0.f;
#pragma unroll
    for (int tt = 0; tt < 8; tt++) {
        int tkn = tok0 + tt;
        if (tkn >= BK) break;
        float zlo = g_tmp1[(size_t)tkn * 64 + lane];
        float zhi = g_tmp1[(size_t)tkn * 64 + 32 + lane];
        zlo = fmaxf(fmaf(zlo, sc_lo, sh_lo), 0.f);
        zhi = fmaxf(fmaf(zhi, sc_hi, sh_hi), 0.f);
        float acc = bias;
#pragma unroll
        for (int c = 0; c < 32; c++)
            acc = fmaf(__shfl_sync(0xffffffffu, zlo, c), wT[c * 32 + lane], acc);
#pragma unroll
        for (int c = 0; c < 32; c++)
            acc = fmaf(__shfl_sync(0xffffffffu, zhi, c), wT[(c + 32) * 32 + lane], acc);
        g_tmp2[(size_t)tkn * 32 + lane] = acc;
        s1 += acc; s2 = fmaf(acc, acc, s2);
    }
    atomicAdd(&ssum[lane], s1); atomicAdd(&ssq[lane], s2);
    __syncthreads();
    if (t < 32) { red_f(&g_st2[t], ssum[t]); red_f(&g_st2[32 + t], ssq[t]); }
}

// ---- mlp3: warp-per-token, lane = channel; butterfly norm; write output ----
__global__ void mlp3_k(const float* __restrict__ g2,
                       const float* __restrict__ b2,
                       float* __restrict__ out,
                       int BK, float invN) {
    __shared__ float scale[32], shift[32];
    int t = threadIdx.x, lane = t & 31, w = t >> 5;
    if (t < 32) {
        float m   = g_st2[t] * invN;
        float var = g_st2[32 + t] * invN - m * m;
        float sc  = g2[t] * rsqrtf(var + EPS);
        scale[t] = sc; shift[t] = b2[t] - m * sc;
    }
    __syncthreads();
    float sc = scale[lane], sh = shift[lane];
    int tok0 = blockIdx.x * 64 + w * 8;
#pragma unroll
    for (int tt = 0; tt < 8; tt++) {
        int tkn = tok0 + tt;
        if (tkn >= BK) break;
        float v = g_tmp2[(size_t)tkn * 32 + lane];
        v = fmaxf(fmaf(v, sc, sh), 0.f);
        float n = v * v;
#pragma unroll
        for (int off = 16; off; off >>= 1)
            n += __shfl_xor_sync(0xffffffffu, n, off);
        float inv = 1.f / fmaxf(sqrtf(n), 1e-8f);
        out[(size_t)tkn * 32 + lane] = v * inv;
    }
}

extern "C" void kernel_launch(void* const* d_in, const int* in_sizes, int n_in,
                              void* d_out, int out_size) {
    const int*   labels = (const int*)  d_in[0];
    const float* fx     = (const float*)d_in[1];
    const float* fy     = (const float*)d_in[2];
    const int*   fidx   = (const int*)  d_in[3];
    int wi = 4;
    const int* nfp = nullptr;
    if (n_in >= 14) {
        nfp = (const int*)d_in[4];
        wi = 6;
    }
    const float* cw = (const float*)d_in[wi + 0];
    const float* cb = (const float*)d_in[wi + 1];
    const float* g1 = (const float*)d_in[wi + 2];
    const float* b1 = (const float*)d_in[wi + 3];
    const float* lw = (const float*)d_in[wi + 4];
    const float* lb = (const float*)d_in[wi + 5];
    const float* g2 = (const float*)d_in[wi + 6];
    const float* b2 = (const float*)d_in[wi + 7];

    int B  = in_sizes[3];
    int Np = in_sizes[0];
    int P  = Np / B;
    int BK = out_size / 32;
    int K  = BK / B;
    int hh = (int)(sqrt((double)P) + 0.5);
    int ww = P / hh;
    float sx = 2.f / (float)(ww - 1);
    float sy = 2.f / (float)(hh - 1);

    zero_k<<<(BK + 255) / 256, 256>>>(BK);

    bool fast = (hh * ww == P) && (hh % 4 == 0) && (P % 4096 == 0) &&
                (K <= 2048) && (hh <= 4096) && (ww <= 4096);
    if (fast) {
        int cpb = P / 4096;
        pool_priv_k<<<B * cpb, 256, K * 16>>>(labels, fx, fy, P, hh, K, cpb);
    } else {
        pool_gl_k<<<(Np + 255) / 256, 256>>>(labels, fx, fy, P, hh, K, Np);
    }

    int gb = (BK + 63) / 64;
    float invN = 1.f / (float)BK;
    mlp1_k<<<gb, 256>>>(fidx, nfp, cw, cb, K, BK, sx, sy);
    mlp2_k<<<gb, 256>>>(lw, lb, g1, b1, BK, invN);
    mlp3_k<<<gb, 256>>>(g2, b2, (float*)d_out, BK, invN);
}